// round 7
// baseline (speedup 1.0000x reference)
#include <cuda_runtime.h>
#include <cstdint>

// ============================================================================
// Grouped GEMM (MoE ParallelExperts): out[T,N] = concat_e( A_e @ W_e^T )
//   A: [16384, 2048] fp32, W: [8, 8192, 2048] fp32, 2048 tokens/expert (static)
//
// Two-phase:
//   1) permute+convert A and W into MMA-fragment-ordered tf32 scratch:
//      512B blocks where thread `lane` reads its 4 mma.sync regs as one LDS.128
//   2) tf32 mma.sync (m16n8k8) GEMM, cp.async 3-stage pipeline.
//      512 threads (16 warps, 4 warps/SMSP) with warp tile 32x64: same tensor
//      floor per SMSP, 2x the latency-hiding warps vs the 256-thread version.
//
// NOTE: harness compiles PTX at target sm_103 (no 'a') -> tcgen05 unavailable;
// mma.sync is the fastest arch-agnostic tensor path.
// R5/R6 failed in the environment (harness-init OOM / container broker), not
// in this code; design unchanged, third attempt.
// ============================================================================

#define M_TOTAL 16384
#define K_TOTAL 2048
#define N_TOTAL 8192
#define NUM_EXPERTS 8
#define M_PER_EXPERT 2048

#define BM 128
#define BN 256
#define BK 32
#define STAGES 3
#define K_ITERS (K_TOTAL / BK)             // 64
#define THREADS 512

#define M_TILES (M_TOTAL / BM)             // 128
#define M_TILES_PER_E (M_PER_EXPERT / BM)  // 16
#define N_TILES (N_TOTAL / BN)             // 32
#define TILES_PER_E (M_TILES_PER_E * N_TILES)
#define GRID_TILES (NUM_EXPERTS * TILES_PER_E)  // 4096

// fragment-ordered stage: A slab 16KB (8 m16-blocks x 4 ks x 512B),
//                         B slab 32KB (32 n8-blocks x 2 ks2 x 512B)
#define A_STAGE_WORDS (BM * BK)            // 4096
#define B_STAGE_WORDS (BN * BK)            // 8192
#define STAGE_WORDS (A_STAGE_WORDS + B_STAGE_WORDS)   // 12288
#define SMEM_BYTES (STAGES * STAGE_WORDS * 4)         // 147456

// warp grid 4(m) x 4(n); warp tile 32x64
#define MF 2   // m-frags of 16 rows
#define NF 8   // n-frags of 8 cols

// ---------------------------------------------------------------- scratch
__device__ uint32_t g_Ac[M_TOTAL * K_TOTAL];                 // 128 MB
__device__ uint32_t g_Wc[NUM_EXPERTS * N_TOTAL * K_TOTAL];   // 512 MB

// ---------------------------------------------------------------- helpers
__device__ __forceinline__ uint32_t smem_u32(const void* p) {
    uint32_t a;
    asm("{ .reg .u64 t; cvta.to.shared.u64 t, %1; cvt.u32.u64 %0, t; }" : "=r"(a) : "l"(p));
    return a;
}

__device__ __forceinline__ void cp_async16(uint32_t dst, const void* src) {
    asm volatile("cp.async.cg.shared.global [%0], [%1], 16;" :: "r"(dst), "l"(src));
}
#define CP_COMMIT() asm volatile("cp.async.commit_group;" ::: "memory")
#define CP_WAIT(n)  asm volatile("cp.async.wait_group %0;" :: "n"(n) : "memory")

__device__ __forceinline__ uint32_t f2tf32(float f) {
    uint32_t u;
    asm("cvt.rna.tf32.f32 %0, %1;" : "=r"(u) : "f"(f));
    return u;
}

__device__ __forceinline__ void mma_tf32(float* c, const uint32_t* a, uint32_t b0, uint32_t b1) {
    asm volatile(
        "mma.sync.aligned.m16n8k8.row.col.f32.tf32.tf32.f32 "
        "{%0,%1,%2,%3}, {%4,%5,%6,%7}, {%8,%9}, {%0,%1,%2,%3};"
        : "+f"(c[0]), "+f"(c[1]), "+f"(c[2]), "+f"(c[3])
        : "r"(a[0]), "r"(a[1]), "r"(a[2]), "r"(a[3]), "r"(b0), "r"(b1));
}

// ---------------------------------------------------------------- permute A
// A_perm block id = ((mt*64 + kc)*8 + mblk)*4 + ks ; block = 512B, one warp.
__global__ void __launch_bounds__(256)
permute_A(const float* __restrict__ A) {
    int wid = (blockIdx.x * blockDim.x + threadIdx.x) >> 5;
    int lane = threadIdx.x & 31;
    int ks = wid & 3;
    int mblk = (wid >> 2) & 7;
    int kc = (wid >> 5) & 63;
    int mt = wid >> 11;
    int g = lane >> 2, tg = lane & 3;
    int r0 = mt * BM + mblk * 16;
    int c0 = kc * BK + ks * 8;
    const float* p = A + (size_t)(r0 + g) * K_TOTAL + c0 + tg;
    uint4 o;
    o.x = f2tf32(p[0]);
    o.y = f2tf32(p[(size_t)8 * K_TOTAL]);
    o.z = f2tf32(p[4]);
    o.w = f2tf32(p[(size_t)8 * K_TOTAL + 4]);
    reinterpret_cast<uint4*>(g_Ac)[(size_t)wid * 32 + lane] = o;
}

// ---------------------------------------------------------------- permute W
// W_perm block id = (((e*32 + nt)*64 + kc)*64 + nblk*2 + ks2) ; 512B, one warp.
__global__ void __launch_bounds__(256)
permute_W(const float* __restrict__ W) {
    int wid = (blockIdx.x * blockDim.x + threadIdx.x) >> 5;
    int lane = threadIdx.x & 31;
    int ks2 = wid & 1;
    int nblk = (wid >> 1) & 31;
    int kc = (wid >> 6) & 63;
    int nt = (wid >> 12) & 31;
    int e = wid >> 17;
    int g = lane >> 2, tg = lane & 3;
    int nrow = nt * BN + nblk * 8 + g;
    int kb = kc * BK + ks2 * 16;
    const float* p = W + ((size_t)e * N_TOTAL + nrow) * K_TOTAL + kb + tg;
    uint4 o;
    o.x = f2tf32(p[0]);
    o.y = f2tf32(p[4]);
    o.z = f2tf32(p[8]);
    o.w = f2tf32(p[12]);
    reinterpret_cast<uint4*>(g_Wc)[(size_t)wid * 32 + lane] = o;
}

// ---------------------------------------------------------------- stage load
__device__ __forceinline__ void load_stage(uint32_t stage_addr, const uint32_t* Aslab,
                                           const uint32_t* Bslab, int tid) {
    const char* asrc = (const char*)Aslab;
#pragma unroll
    for (int i = 0; i < 2; i++) {               // A: 16KB = 1024 chunks / 512 thr
        int q = tid + i * THREADS;
        cp_async16(stage_addr + (uint32_t)q * 16, asrc + (size_t)q * 16);
    }
    const char* bsrc = (const char*)Bslab;
    uint32_t bdst = stage_addr + A_STAGE_WORDS * 4;
#pragma unroll
    for (int i = 0; i < 4; i++) {               // B: 32KB = 2048 chunks
        int q = tid + i * THREADS;
        cp_async16(bdst + (uint32_t)q * 16, bsrc + (size_t)q * 16);
    }
}

// ---------------------------------------------------------------- kernel
__global__ void __launch_bounds__(THREADS, 1)
moe_tf32_mma(float* __restrict__ out) {
    extern __shared__ uint32_t smem[];
    uint32_t sb = smem_u32(smem);
    int tid = threadIdx.x;
    int lane = tid & 31;
    int warp = tid >> 5;
    int wm = warp >> 2;        // 0..3
    int wn = warp & 3;         // 0..3
    int g = lane >> 2;
    int tg = lane & 3;

    // tile mapping: expert-major, m fast within expert
    int b = blockIdx.x;
    int e = b / TILES_PER_E;
    int loc = b % TILES_PER_E;
    int m_idx = loc & (M_TILES_PER_E - 1);
    int n_idx = loc >> 4;
    int mt = e * M_TILES_PER_E + m_idx;
    int m0 = mt * BM;
    int n0 = n_idx * BN;

    const uint32_t* Abase = g_Ac + (size_t)mt * 64 * A_STAGE_WORDS;
    const uint32_t* Bbase = g_Wc + ((size_t)(e * N_TILES + n_idx)) * 64 * B_STAGE_WORDS;

    float acc[MF][NF][4];
#pragma unroll
    for (int mf = 0; mf < MF; mf++)
#pragma unroll
        for (int nf = 0; nf < NF; nf++)
#pragma unroll
            for (int r = 0; r < 4; r++) acc[mf][nf][r] = 0.0f;

    // prologue: fill STAGES-1 stages
    load_stage(sb, Abase, Bbase, tid);
    CP_COMMIT();
    load_stage(sb + STAGE_WORDS * 4, Abase + A_STAGE_WORDS, Bbase + B_STAGE_WORDS, tid);
    CP_COMMIT();

    for (int k = 0; k < K_ITERS; k++) {
        CP_WAIT(1);
        __syncthreads();

        if (k + STAGES - 1 < K_ITERS) {
            int kn = k + 2;
            load_stage(sb + (uint32_t)((kn % 3) * (STAGE_WORDS * 4)),
                       Abase + (size_t)kn * A_STAGE_WORDS,
                       Bbase + (size_t)kn * B_STAGE_WORDS, tid);
        }
        CP_COMMIT();  // always commit (possibly empty) to keep accounting exact

        const uint4* sA4 = reinterpret_cast<const uint4*>(smem + (k % 3) * STAGE_WORDS);
        const uint4* sB4 = sA4 + (A_STAGE_WORDS / 4);

#pragma unroll
        for (int ks2 = 0; ks2 < 2; ks2++) {
            uint4 bf[NF];
#pragma unroll
            for (int nf = 0; nf < NF; nf++)
                bf[nf] = sB4[((wn * 8 + nf) * 2 + ks2) * 32 + lane];
#pragma unroll
            for (int ksi = 0; ksi < 2; ksi++) {
                int ks = ks2 * 2 + ksi;
                uint4 af[MF];
#pragma unroll
                for (int mf = 0; mf < MF; mf++)
                    af[mf] = sA4[((wm * 2 + mf) * 4 + ks) * 32 + lane];
#pragma unroll
                for (int nf = 0; nf < NF; nf++) {
                    uint32_t b0 = ksi ? bf[nf].z : bf[nf].x;
                    uint32_t b1 = ksi ? bf[nf].w : bf[nf].y;
#pragma unroll
                    for (int mf = 0; mf < MF; mf++)
                        mma_tf32(acc[mf][nf], reinterpret_cast<const uint32_t*>(&af[mf]), b0, b1);
                }
            }
        }
    }

    // epilogue: direct STG.64 per c-pair
    int mrow_base = m0 + wm * 32;
    int ncol_base = n0 + wn * 64;
#pragma unroll
    for (int mf = 0; mf < MF; mf++) {
        float* prow = out + (size_t)(mrow_base + mf * 16 + g) * N_TOTAL + ncol_base + 2 * tg;
#pragma unroll
        for (int nf = 0; nf < NF; nf++) {
            float2 v0 = make_float2(acc[mf][nf][0], acc[mf][nf][1]);
            float2 v1 = make_float2(acc[mf][nf][2], acc[mf][nf][3]);
            *reinterpret_cast<float2*>(prow + nf * 8) = v0;
            *reinterpret_cast<float2*>(prow + nf * 8 + 8 * N_TOTAL) = v1;
        }
    }
}

// ---------------------------------------------------------------- launch
extern "C" void kernel_launch(void* const* d_in, const int* in_sizes, int n_in,
                              void* d_out, int out_size) {
    const float* A = (const float*)d_in[0];   // [16384, 2048]
    const float* W = (const float*)d_in[1];   // [8, 8192, 2048]
    float* out = (float*)d_out;               // [16384, 8192]
    (void)in_sizes; (void)n_in; (void)out_size;

    // phase 1: permute+convert to fragment-ordered tf32 scratch
    {
        int a_blocks = M_TILES * 64 * 8 * 4;              // 262144 warps
        int w_blocks = NUM_EXPERTS * N_TILES * 64 * 64;   // 1048576 warps
        permute_A<<<a_blocks / 8, 256>>>(A);
        permute_W<<<w_blocks / 8, 256>>>(W);
    }

    // phase 2: GEMM (same stream -> ordered after conversion)
    cudaFuncSetAttribute(moe_tf32_mma, cudaFuncAttributeMaxDynamicSharedMemorySize,
                         (int)SMEM_BYTES);
    moe_tf32_mma<<<GRID_TILES, THREADS, SMEM_BYTES>>>(out);
}

// round 9
// speedup vs baseline: 1.0490x; 1.0490x over previous
#include <cuda_runtime.h>
#include <cstdint>

// ============================================================================
// Grouped GEMM (MoE ParallelExperts): out[T,N] = concat_e( A_e @ W_e^T )
//   A: [16384, 2048] fp32, W: [8, 8192, 2048] fp32, 2048 tokens/expert (static)
//
// Two-phase:
//   1) permute+convert A and W into MMA-fragment-ordered tf32 scratch:
//      512B blocks where thread `lane` reads its 4 mma.sync regs as one LDS.128
//   2) tf32 mma.sync (m16n8k8) GEMM, 256 threads, warp tile 64x64.
//      BK=64, 2-stage cp.async pipeline: 32 K-iters instead of 64 -> halves
//      the per-iteration structural overhead (barrier + wait + issue bursts)
//      that R7 showed occupancy cannot hide.
//
// NOTE: harness compiles PTX at target sm_103 (no 'a') -> tcgen05 unavailable;
// mma.sync is the fastest arch-agnostic tensor path.
// ============================================================================

#define M_TOTAL 16384
#define K_TOTAL 2048
#define N_TOTAL 8192
#define NUM_EXPERTS 8
#define M_PER_EXPERT 2048

#define BM 128
#define BN 256
#define BK 64
#define K_ITERS (K_TOTAL / BK)             // 32
#define THREADS 256

#define M_TILES (M_TOTAL / BM)             // 128
#define M_TILES_PER_E (M_PER_EXPERT / BM)  // 16
#define N_TILES (N_TOTAL / BN)             // 32
#define TILES_PER_E (M_TILES_PER_E * N_TILES)
#define GRID_TILES (NUM_EXPERTS * TILES_PER_E)  // 4096

// scratch kc-slab granularity stays BK=32 (64 slabs per tile, contiguous)
#define A_SLAB_WORDS (BM * 32)             // 4096
#define B_SLAB_WORDS (BN * 32)             // 8192
// BK=64 stage = 2 consecutive slabs
#define A_STAGE_WORDS (2 * A_SLAB_WORDS)   // 8192  (32 KB)
#define B_STAGE_WORDS (2 * B_SLAB_WORDS)   // 16384 (64 KB)
#define STAGE_WORDS (A_STAGE_WORDS + B_STAGE_WORDS)   // 24576
#define SMEM_BYTES (2 * STAGE_WORDS * 4)              // 196608

// warp grid 2(m) x 4(n); warp tile 64x64
#define MF 4   // m-frags of 16 rows
#define NF 8   // n-frags of 8 cols

// ---------------------------------------------------------------- scratch
__device__ uint32_t g_Ac[M_TOTAL * K_TOTAL];                 // 128 MB
__device__ uint32_t g_Wc[NUM_EXPERTS * N_TOTAL * K_TOTAL];   // 512 MB

// ---------------------------------------------------------------- helpers
__device__ __forceinline__ uint32_t smem_u32(const void* p) {
    uint32_t a;
    asm("{ .reg .u64 t; cvta.to.shared.u64 t, %1; cvt.u32.u64 %0, t; }" : "=r"(a) : "l"(p));
    return a;
}

__device__ __forceinline__ void cp_async16(uint32_t dst, const void* src) {
    asm volatile("cp.async.cg.shared.global [%0], [%1], 16;" :: "r"(dst), "l"(src));
}
#define CP_COMMIT() asm volatile("cp.async.commit_group;" ::: "memory")
#define CP_WAIT(n)  asm volatile("cp.async.wait_group %0;" :: "n"(n) : "memory")

__device__ __forceinline__ uint32_t f2tf32(float f) {
    uint32_t u;
    asm("cvt.rna.tf32.f32 %0, %1;" : "=r"(u) : "f"(f));
    return u;
}

__device__ __forceinline__ void mma_tf32(float* c, const uint32_t* a, uint32_t b0, uint32_t b1) {
    asm volatile(
        "mma.sync.aligned.m16n8k8.row.col.f32.tf32.tf32.f32 "
        "{%0,%1,%2,%3}, {%4,%5,%6,%7}, {%8,%9}, {%0,%1,%2,%3};"
        : "+f"(c[0]), "+f"(c[1]), "+f"(c[2]), "+f"(c[3])
        : "r"(a[0]), "r"(a[1]), "r"(a[2]), "r"(a[3]), "r"(b0), "r"(b1));
}

// ---------------------------------------------------------------- permute A
// A_perm block id = ((mt*64 + kc)*8 + mblk)*4 + ks ; block = 512B, one warp.
__global__ void __launch_bounds__(256)
permute_A(const float* __restrict__ A) {
    int wid = (blockIdx.x * blockDim.x + threadIdx.x) >> 5;
    int lane = threadIdx.x & 31;
    int ks = wid & 3;
    int mblk = (wid >> 2) & 7;
    int kc = (wid >> 5) & 63;
    int mt = wid >> 11;
    int g = lane >> 2, tg = lane & 3;
    int r0 = mt * BM + mblk * 16;
    int c0 = kc * 32 + ks * 8;
    const float* p = A + (size_t)(r0 + g) * K_TOTAL + c0 + tg;
    uint4 o;
    o.x = f2tf32(p[0]);
    o.y = f2tf32(p[(size_t)8 * K_TOTAL]);
    o.z = f2tf32(p[4]);
    o.w = f2tf32(p[(size_t)8 * K_TOTAL + 4]);
    reinterpret_cast<uint4*>(g_Ac)[(size_t)wid * 32 + lane] = o;
}

// ---------------------------------------------------------------- permute W
// W_perm block id = (((e*32 + nt)*64 + kc)*64 + nblk*2 + ks2) ; 512B, one warp.
__global__ void __launch_bounds__(256)
permute_W(const float* __restrict__ W) {
    int wid = (blockIdx.x * blockDim.x + threadIdx.x) >> 5;
    int lane = threadIdx.x & 31;
    int ks2 = wid & 1;
    int nblk = (wid >> 1) & 31;
    int kc = (wid >> 6) & 63;
    int nt = (wid >> 12) & 31;
    int e = wid >> 17;
    int g = lane >> 2, tg = lane & 3;
    int nrow = nt * BN + nblk * 8 + g;
    int kb = kc * 32 + ks2 * 16;
    const float* p = W + ((size_t)e * N_TOTAL + nrow) * K_TOTAL + kb + tg;
    uint4 o;
    o.x = f2tf32(p[0]);
    o.y = f2tf32(p[4]);
    o.z = f2tf32(p[8]);
    o.w = f2tf32(p[12]);
    reinterpret_cast<uint4*>(g_Wc)[(size_t)wid * 32 + lane] = o;
}

// ---------------------------------------------------------------- stage load
// BK=64 stage = contiguous 32KB A + contiguous 64KB B from permuted scratch
__device__ __forceinline__ void load_stage(uint32_t stage_addr, const uint32_t* Aslab,
                                           const uint32_t* Bslab, int tid) {
    const char* asrc = (const char*)Aslab;
#pragma unroll
    for (int i = 0; i < 8; i++) {               // A: 32KB = 2048 chunks / 256 thr
        int q = tid + i * THREADS;
        cp_async16(stage_addr + (uint32_t)q * 16, asrc + (size_t)q * 16);
    }
    const char* bsrc = (const char*)Bslab;
    uint32_t bdst = stage_addr + A_STAGE_WORDS * 4;
#pragma unroll
    for (int i = 0; i < 16; i++) {              // B: 64KB = 4096 chunks
        int q = tid + i * THREADS;
        cp_async16(bdst + (uint32_t)q * 16, bsrc + (size_t)q * 16);
    }
}

// ---------------------------------------------------------------- kernel
__global__ void __launch_bounds__(THREADS, 1)
moe_tf32_mma(float* __restrict__ out) {
    extern __shared__ uint32_t smem[];
    uint32_t sb = smem_u32(smem);
    int tid = threadIdx.x;
    int lane = tid & 31;
    int warp = tid >> 5;
    int wm = warp >> 2;        // 0..1
    int wn = warp & 3;         // 0..3
    int g = lane >> 2;
    int tg = lane & 3;

    // tile mapping: expert-major, m fast within expert
    int b = blockIdx.x;
    int e = b / TILES_PER_E;
    int loc = b % TILES_PER_E;
    int m_idx = loc & (M_TILES_PER_E - 1);
    int n_idx = loc >> 4;
    int mt = e * M_TILES_PER_E + m_idx;
    int m0 = mt * BM;
    int n0 = n_idx * BN;

    const uint32_t* Abase = g_Ac + (size_t)mt * 64 * A_SLAB_WORDS;
    const uint32_t* Bbase = g_Wc + ((size_t)(e * N_TILES + n_idx)) * 64 * B_SLAB_WORDS;

    float acc[MF][NF][4];
#pragma unroll
    for (int mf = 0; mf < MF; mf++)
#pragma unroll
        for (int nf = 0; nf < NF; nf++)
#pragma unroll
            for (int r = 0; r < 4; r++) acc[mf][nf][r] = 0.0f;

    // prologue: fill stage 0
    load_stage(sb, Abase, Bbase, tid);
    CP_COMMIT();

    for (int k = 0; k < K_ITERS; k++) {
        // stage k&1 was committed last (iter k-1 or prologue): wait all
        CP_WAIT(0);
        __syncthreads();   // all warps done reading stage (k-1)&1 + data visible

        if (k + 1 < K_ITERS) {
            load_stage(sb + (uint32_t)(((k + 1) & 1) * (STAGE_WORDS * 4)),
                       Abase + (size_t)(k + 1) * A_STAGE_WORDS,
                       Bbase + (size_t)(k + 1) * B_STAGE_WORDS, tid);
            CP_COMMIT();   // overlaps with the compute below
        }

        const uint4* sA4 = reinterpret_cast<const uint4*>(smem + (k & 1) * STAGE_WORDS);
        const uint4* sB4 = sA4 + (A_STAGE_WORDS / 4);

#pragma unroll
        for (int ks2 = 0; ks2 < 4; ks2++) {      // 4 B-blocks of k16 across BK=64
            int kh = ks2 >> 1;                   // which kc-slab (0/1)
            int k2i = ks2 & 1;                   // B block within slab
            uint4 bf[NF];
#pragma unroll
            for (int nf = 0; nf < NF; nf++)
                bf[nf] = sB4[kh * 2048 + ((wn * 8 + nf) * 2 + k2i) * 32 + lane];
#pragma unroll
            for (int ksi = 0; ksi < 2; ksi++) {
                int ksin = k2i * 2 + ksi;        // A ks within slab (0..3)
                uint4 af[MF];
#pragma unroll
                for (int mf = 0; mf < MF; mf++)
                    af[mf] = sA4[kh * 1024 + ((wm * 4 + mf) * 4 + ksin) * 32 + lane];
#pragma unroll
                for (int nf = 0; nf < NF; nf++) {
                    uint32_t b0 = ksi ? bf[nf].z : bf[nf].x;
                    uint32_t b1 = ksi ? bf[nf].w : bf[nf].y;
#pragma unroll
                    for (int mf = 0; mf < MF; mf++)
                        mma_tf32(acc[mf][nf], reinterpret_cast<const uint32_t*>(&af[mf]), b0, b1);
                }
            }
        }
    }

    // epilogue: direct STG.64 per c-pair
    int mrow_base = m0 + wm * 64;
    int ncol_base = n0 + wn * 64;
#pragma unroll
    for (int mf = 0; mf < MF; mf++) {
        float* prow = out + (size_t)(mrow_base + mf * 16 + g) * N_TOTAL + ncol_base + 2 * tg;
#pragma unroll
        for (int nf = 0; nf < NF; nf++) {
            float2 v0 = make_float2(acc[mf][nf][0], acc[mf][nf][1]);
            float2 v1 = make_float2(acc[mf][nf][2], acc[mf][nf][3]);
            *reinterpret_cast<float2*>(prow + nf * 8) = v0;
            *reinterpret_cast<float2*>(prow + nf * 8 + 8 * N_TOTAL) = v1;
        }
    }
}

// ---------------------------------------------------------------- launch
extern "C" void kernel_launch(void* const* d_in, const int* in_sizes, int n_in,
                              void* d_out, int out_size) {
    const float* A = (const float*)d_in[0];   // [16384, 2048]
    const float* W = (const float*)d_in[1];   // [8, 8192, 2048]
    float* out = (float*)d_out;               // [16384, 8192]
    (void)in_sizes; (void)n_in; (void)out_size;

    // phase 1: permute+convert to fragment-ordered tf32 scratch
    {
        int a_blocks = M_TILES * 64 * 8 * 4;              // 262144 warps
        int w_blocks = NUM_EXPERTS * N_TILES * 64 * 64;   // 1048576 warps
        permute_A<<<a_blocks / 8, 256>>>(A);
        permute_W<<<w_blocks / 8, 256>>>(W);
    }

    // phase 2: GEMM (same stream -> ordered after conversion)
    cudaFuncSetAttribute(moe_tf32_mma, cudaFuncAttributeMaxDynamicSharedMemorySize,
                         (int)SMEM_BYTES);
    moe_tf32_mma<<<GRID_TILES, THREADS, SMEM_BYTES>>>(out);
}

// round 14
// speedup vs baseline: 1.1673x; 1.1128x over previous
#include <cuda_runtime.h>
#include <cstdint>

// ============================================================================
// Grouped GEMM (MoE ParallelExperts): out[T,N] = concat_e( A_e @ W_e^T )
//   A: [16384, 2048] fp32, W: [8, 8192, 2048] fp32, 2048 tokens/expert (static)
//
// Two-phase:
//   1) permute+convert A and W into MMA-fragment-ordered tf32 scratch
//      (512B blocks; lane reads its 4 mma.sync regs as one LDS.128)
//   2) tf32 mma.sync (m16n8k8) GEMM, 256 threads, warp tile 64x64, BK=64,
//      2-stage pipeline fed by cp.async.bulk (TMA bulk, base-ISA sm_90+) +
//      mbarrier expect_tx: 2 bulk copies/stage instead of 192 LDGSTS
//      warp-instructions -> frees LSU issue slots for the tensor pipe.
//
// NOTE: harness compiles PTX at target sm_103 (no 'a') -> tcgen05 unavailable;
// mma.sync + cp.async.bulk are the fastest base-ISA paths.
// R11 failed in the broker (container failed twice, pre-compile); design
// unchanged, resubmission.
// ============================================================================

#define M_TOTAL 16384
#define K_TOTAL 2048
#define N_TOTAL 8192
#define NUM_EXPERTS 8
#define M_PER_EXPERT 2048

#define BM 128
#define BN 256
#define BK 64
#define K_ITERS (K_TOTAL / BK)             // 32
#define THREADS 256

#define M_TILES (M_TOTAL / BM)             // 128
#define M_TILES_PER_E (M_PER_EXPERT / BM)  // 16
#define N_TILES (N_TOTAL / BN)             // 32
#define TILES_PER_E (M_TILES_PER_E * N_TILES)
#define GRID_TILES (NUM_EXPERTS * TILES_PER_E)  // 4096

// scratch kc-slab granularity stays BK=32 (64 slabs per tile, contiguous)
#define A_SLAB_WORDS (BM * 32)             // 4096
#define B_SLAB_WORDS (BN * 32)             // 8192
// BK=64 stage = 2 consecutive slabs
#define A_STAGE_WORDS (2 * A_SLAB_WORDS)   // 8192  (32 KB)
#define B_STAGE_WORDS (2 * B_SLAB_WORDS)   // 16384 (64 KB)
#define STAGE_WORDS (A_STAGE_WORDS + B_STAGE_WORDS)   // 24576
#define STAGE_BYTES (STAGE_WORDS * 4)                 // 98304
#define SMEM_BYTES (2 * STAGE_BYTES)                  // 196608

// warp grid 2(m) x 4(n); warp tile 64x64
#define MF 4   // m-frags of 16 rows
#define NF 8   // n-frags of 8 cols

// ---------------------------------------------------------------- scratch
__device__ uint32_t g_Ac[M_TOTAL * K_TOTAL];                 // 128 MB
__device__ uint32_t g_Wc[NUM_EXPERTS * N_TOTAL * K_TOTAL];   // 512 MB

// ---------------------------------------------------------------- helpers
__device__ __forceinline__ uint32_t smem_u32(const void* p) {
    uint32_t a;
    asm("{ .reg .u64 t; cvta.to.shared.u64 t, %1; cvt.u32.u64 %0, t; }" : "=r"(a) : "l"(p));
    return a;
}

__device__ __forceinline__ uint32_t f2tf32(float f) {
    uint32_t u;
    asm("cvt.rna.tf32.f32 %0, %1;" : "=r"(u) : "f"(f));
    return u;
}

__device__ __forceinline__ void mma_tf32(float* c, const uint32_t* a, uint32_t b0, uint32_t b1) {
    asm volatile(
        "mma.sync.aligned.m16n8k8.row.col.f32.tf32.tf32.f32 "
        "{%0,%1,%2,%3}, {%4,%5,%6,%7}, {%8,%9}, {%0,%1,%2,%3};"
        : "+f"(c[0]), "+f"(c[1]), "+f"(c[2]), "+f"(c[3])
        : "r"(a[0]), "r"(a[1]), "r"(a[2]), "r"(a[3]), "r"(b0), "r"(b1));
}

#define MBARRIER_INIT(addr, count) \
    asm volatile("mbarrier.init.shared.b64 [%0], %1;" :: "r"((uint32_t)(addr)), "r"((uint32_t)(count)) : "memory")
#define MBARRIER_EXPECT_TX(addr, bytes) \
    asm volatile("mbarrier.arrive.expect_tx.shared.b64 _, [%0], %1;" :: "r"((uint32_t)(addr)), "r"((uint32_t)(bytes)) : "memory")

__device__ __forceinline__ void bulk_g2s(uint32_t dst, const void* src, uint32_t bytes,
                                         uint32_t mbar) {
    asm volatile(
        "cp.async.bulk.shared::cluster.global.mbarrier::complete_tx::bytes [%0], [%1], %2, [%3];"
        :: "r"(dst), "l"(src), "r"(bytes), "r"(mbar) : "memory");
}

#define MBARRIER_WAIT_PARITY(mbar_addr, phase_parity) do {                                   \
    uint32_t _mbar = (uint32_t)(mbar_addr);                                                  \
    uint32_t _parity = (uint32_t)(phase_parity);                                             \
    uint32_t _done;                                                                          \
    asm volatile(                                                                            \
        "{\n\t.reg .pred p;\n\t"                                                             \
        "mbarrier.try_wait.parity.acquire.cta.shared::cta.b64 p, [%1], %2;\n\t"              \
        "selp.b32 %0, 1, 0, p;\n\t}"                                                         \
        : "=r"(_done) : "r"(_mbar), "r"(_parity) : "memory");                                \
    if (!_done) {                                                                            \
        asm volatile(                                                                        \
            "{\n\t.reg .pred P1;\n\t"                                                        \
            "WAIT_LOOP_%=:\n\t"                                                              \
            "mbarrier.try_wait.parity.acquire.cta.shared::cta.b64 P1, [%0], %1, 0x989680;\n\t" \
            "@P1 bra.uni WAIT_DONE_%=;\n\t"                                                  \
            "bra.uni WAIT_LOOP_%=;\n\t"                                                      \
            "WAIT_DONE_%=:\n\t}"                                                             \
            :: "r"(_mbar), "r"(_parity) : "memory");                                         \
    }                                                                                        \
} while (0)

// ---------------------------------------------------------------- permute A
// A_perm block id = ((mt*64 + kc)*8 + mblk)*4 + ks ; block = 512B, one warp.
__global__ void __launch_bounds__(256)
permute_A(const float* __restrict__ A) {
    int wid = (blockIdx.x * blockDim.x + threadIdx.x) >> 5;
    int lane = threadIdx.x & 31;
    int ks = wid & 3;
    int mblk = (wid >> 2) & 7;
    int kc = (wid >> 5) & 63;
    int mt = wid >> 11;
    int g = lane >> 2, tg = lane & 3;
    int r0 = mt * BM + mblk * 16;
    int c0 = kc * 32 + ks * 8;
    const float* p = A + (size_t)(r0 + g) * K_TOTAL + c0 + tg;
    uint4 o;
    o.x = f2tf32(p[0]);
    o.y = f2tf32(p[(size_t)8 * K_TOTAL]);
    o.z = f2tf32(p[4]);
    o.w = f2tf32(p[(size_t)8 * K_TOTAL + 4]);
    reinterpret_cast<uint4*>(g_Ac)[(size_t)wid * 32 + lane] = o;
}

// ---------------------------------------------------------------- permute W
// W_perm block id = (((e*32 + nt)*64 + kc)*64 + nblk*2 + ks2) ; 512B, one warp.
__global__ void __launch_bounds__(256)
permute_W(const float* __restrict__ W) {
    int wid = (blockIdx.x * blockDim.x + threadIdx.x) >> 5;
    int lane = threadIdx.x & 31;
    int ks2 = wid & 1;
    int nblk = (wid >> 1) & 31;
    int kc = (wid >> 6) & 63;
    int nt = (wid >> 12) & 31;
    int e = wid >> 17;
    int g = lane >> 2, tg = lane & 3;
    int nrow = nt * BN + nblk * 8 + g;
    int kb = kc * 32 + ks2 * 16;
    const float* p = W + ((size_t)e * N_TOTAL + nrow) * K_TOTAL + kb + tg;
    uint4 o;
    o.x = f2tf32(p[0]);
    o.y = f2tf32(p[4]);
    o.z = f2tf32(p[8]);
    o.w = f2tf32(p[12]);
    reinterpret_cast<uint4*>(g_Wc)[(size_t)wid * 32 + lane] = o;
}

// ---------------------------------------------------------------- kernel
__global__ void __launch_bounds__(THREADS, 1)
moe_tf32_mma(float* __restrict__ out) {
    extern __shared__ uint32_t smem[];
    __shared__ __align__(8) uint64_t mbar_s[2];
    uint32_t sb = smem_u32(smem);
    uint32_t mb = smem_u32(mbar_s);
    int tid = threadIdx.x;
    int lane = tid & 31;
    int warp = tid >> 5;
    int wm = warp >> 2;        // 0..1
    int wn = warp & 3;         // 0..3
    int g = lane >> 2;
    int tg = lane & 3;

    // tile mapping: expert-major, m fast within expert
    int b = blockIdx.x;
    int e = b / TILES_PER_E;
    int loc = b % TILES_PER_E;
    int m_idx = loc & (M_TILES_PER_E - 1);
    int n_idx = loc >> 4;
    int mt = e * M_TILES_PER_E + m_idx;
    int m0 = mt * BM;
    int n0 = n_idx * BN;

    const uint32_t* Abase = g_Ac + (size_t)mt * 64 * A_SLAB_WORDS;
    const uint32_t* Bbase = g_Wc + ((size_t)(e * N_TILES + n_idx)) * 64 * B_SLAB_WORDS;

    float acc[MF][NF][4];
#pragma unroll
    for (int mf = 0; mf < MF; mf++)
#pragma unroll
        for (int nf = 0; nf < NF; nf++)
#pragma unroll
            for (int r = 0; r < 4; r++) acc[mf][nf][r] = 0.0f;

    if (tid == 0) {
        MBARRIER_INIT(mb + 0, 1);
        MBARRIER_INIT(mb + 8, 1);
    }
    __syncthreads();

    // prologue: bulk-load stage 0
    if (tid == 0) {
        MBARRIER_EXPECT_TX(mb + 0, STAGE_BYTES);
        bulk_g2s(sb, Abase, A_STAGE_WORDS * 4, mb + 0);
        bulk_g2s(sb + A_STAGE_WORDS * 4, Bbase, B_STAGE_WORDS * 4, mb + 0);
    }

    for (int k = 0; k < K_ITERS; k++) {
        int s = k & 1;
        uint32_t ph = (uint32_t)(k >> 1) & 1u;
        MBARRIER_WAIT_PARITY(mb + 8 * s, ph);
        __syncthreads();   // all warps done reading the other stage before overwrite

        if (k + 1 < K_ITERS) {
            if (tid == 0) {
                int sn = (k + 1) & 1;
                uint32_t dst = sb + (uint32_t)(sn * STAGE_BYTES);
                MBARRIER_EXPECT_TX(mb + 8 * sn, STAGE_BYTES);
                bulk_g2s(dst, Abase + (size_t)(k + 1) * A_STAGE_WORDS,
                         A_STAGE_WORDS * 4, mb + 8 * sn);
                bulk_g2s(dst + A_STAGE_WORDS * 4, Bbase + (size_t)(k + 1) * B_STAGE_WORDS,
                         B_STAGE_WORDS * 4, mb + 8 * sn);
            }
        }

        const uint4* sA4 = reinterpret_cast<const uint4*>(smem + s * STAGE_WORDS);
        const uint4* sB4 = sA4 + (A_STAGE_WORDS / 4);

#pragma unroll
        for (int ks2 = 0; ks2 < 4; ks2++) {      // 4 B-blocks of k16 across BK=64
            int kh = ks2 >> 1;                   // which kc-slab (0/1)
            int k2i = ks2 & 1;                   // B block within slab
            uint4 bf[NF];
#pragma unroll
            for (int nf = 0; nf < NF; nf++)
                bf[nf] = sB4[kh * 2048 + ((wn * 8 + nf) * 2 + k2i) * 32 + lane];
#pragma unroll
            for (int ksi = 0; ksi < 2; ksi++) {
                int ksin = k2i * 2 + ksi;        // A ks within slab (0..3)
                uint4 af[MF];
#pragma unroll
                for (int mf = 0; mf < MF; mf++)
                    af[mf] = sA4[kh * 1024 + ((wm * 4 + mf) * 4 + ksin) * 32 + lane];
#pragma unroll
                for (int nf = 0; nf < NF; nf++) {
                    uint32_t b0 = ksi ? bf[nf].z : bf[nf].x;
                    uint32_t b1 = ksi ? bf[nf].w : bf[nf].y;
#pragma unroll
                    for (int mf = 0; mf < MF; mf++)
                        mma_tf32(acc[mf][nf], reinterpret_cast<const uint32_t*>(&af[mf]), b0, b1);
                }
            }
        }
    }

    // epilogue: direct STG.64 per c-pair
    int mrow_base = m0 + wm * 64;
    int ncol_base = n0 + wn * 64;
#pragma unroll
    for (int mf = 0; mf < MF; mf++) {
        float* prow = out + (size_t)(mrow_base + mf * 16 + g) * N_TOTAL + ncol_base + 2 * tg;
#pragma unroll
        for (int nf = 0; nf < NF; nf++) {
            float2 v0 = make_float2(acc[mf][nf][0], acc[mf][nf][1]);
            float2 v1 = make_float2(acc[mf][nf][2], acc[mf][nf][3]);
            *reinterpret_cast<float2*>(prow + nf * 8) = v0;
            *reinterpret_cast<float2*>(prow + nf * 8 + 8 * N_TOTAL) = v1;
        }
    }
}

// ---------------------------------------------------------------- launch
extern "C" void kernel_launch(void* const* d_in, const int* in_sizes, int n_in,
                              void* d_out, int out_size) {
    const float* A = (const float*)d_in[0];   // [16384, 2048]
    const float* W = (const float*)d_in[1];   // [8, 8192, 2048]
    float* out = (float*)d_out;               // [16384, 8192]
    (void)in_sizes; (void)n_in; (void)out_size;

    // phase 1: permute+convert to fragment-ordered tf32 scratch
    {
        int a_blocks = M_TILES * 64 * 8 * 4;              // 262144 warps
        int w_blocks = NUM_EXPERTS * N_TILES * 64 * 64;   // 1048576 warps
        permute_A<<<a_blocks / 8, 256>>>(A);
        permute_W<<<w_blocks / 8, 256>>>(W);
    }

    // phase 2: GEMM (same stream -> ordered after conversion)
    cudaFuncSetAttribute(moe_tf32_mma, cudaFuncAttributeMaxDynamicSharedMemorySize,
                         (int)SMEM_BYTES);
    moe_tf32_mma<<<GRID_TILES, THREADS, SMEM_BYTES>>>(out);
}